// round 15
// baseline (speedup 1.0000x reference)
#include <cuda_runtime.h>

#define S 26
#define D 7
#define DA 11
#define V 29
#define NT 544                 // 17 warps
#define TRI (S*(S+1)/2)        // 351
#define VWB 352                // vw work starts at warp boundary
#define LOG2E 1.4426950408889634f

__device__ __forceinline__ float ex2(float x) {
    float y; asm("ex2.approx.f32 %0, %1;" : "=f"(y) : "f"(x)); return y;
}
__device__ __forceinline__ float rcpa(float x) {
    float y; asm("rcp.approx.f32 %0, %1;" : "=f"(y) : "f"(x)); return y;
}

__global__ __launch_bounds__(NT, 1)
void bes_transformer_kernel(
    const int*   __restrict__ x,
    const float* __restrict__ emb_table,
    const float* __restrict__ pos,
    const float* __restrict__ wk0, const float* __restrict__ bk0,
    const float* __restrict__ wq0, const float* __restrict__ bq0,
    const float* __restrict__ wv0, const float* __restrict__ bv0,
    const float* __restrict__ wf0, const float* __restrict__ bf0,
    const float* __restrict__ wk1, const float* __restrict__ bk1,
    const float* __restrict__ wq1, const float* __restrict__ bq1,
    const float* __restrict__ wv1, const float* __restrict__ bv1,
    const float* __restrict__ wf1, const float* __restrict__ bf1,
    const float* __restrict__ wout, const float* __restrict__ bout,
    float* __restrict__ out)
{
    __shared__ float h[S][D];
    __shared__ float k[S][DA];
    __shared__ float q[S][DA];    // pre-scaled by log2(e)
    __shared__ float v[S][DA];
    __shared__ float att[S][S];   // lower triangle valid; upper garbage
    __shared__ float vw[S][D];    // v @ wf^T

    const int t = threadIdx.x;

    // packed lower-triangle coords (t < TRI)
    int tr = 0, tc = 0;
    if (t < TRI) {
        tr = (int)((sqrtf(8.f * (float)t + 1.f) - 1.f) * 0.5f);
        if (t < tr * (tr + 1) / 2) tr--;
        if (t >= (tr + 1) * (tr + 2) / 2) tr++;
        tc = t - tr * (tr + 1) / 2;
    }

    // ===== entry-time register prefetch per role =========================
    // QKV role (t < 286): row a = t % 11 of the six 11x7 matrices.
    float pk0[D], pq0[D], pv0[D], pk1[D], pq1[D], pv1[D];
    float bk0r = 0.f, bq0r = 0.f, bv0r = 0.f, bk1r = 0.f, bq1r = 0.f, bv1r = 0.f;
    if (t < S * DA) {
        int a = t % DA;
        #pragma unroll
        for (int d = 0; d < D; d++) {
            pk0[d] = wk0[a * D + d];
            pq0[d] = wq0[a * D + d];
            pv0[d] = wv0[a * D + d];
            pk1[d] = wk1[a * D + d];
            pq1[d] = wq1[a * D + d];
            pv1[d] = wv1[a * D + d];
        }
        bk0r = bk0[a]; bq0r = bq0[a]; bv0r = bv0[a];
        bk1r = bk1[a]; bq1r = bq1[a]; bv1r = bv1[a];
    }
    // vw role (t in [352, 534)): wf row d = (t-352) % 7.
    float pw0[DA], pw1[DA];
    if (t >= VWB && t < VWB + S * D) {
        int d = (t - VWB) % D;
        #pragma unroll
        for (int a = 0; a < DA; a++) {
            pw0[a] = wf0[d * DA + a];
            pw1[a] = wf1[d * DA + a];
        }
    }
    // h role (t < 182): biases only.
    float bf0r = 0.f, bf1r = 0.f;
    if (t < S * D) { bf0r = bf0[t % D]; bf1r = bf1[t % D]; }
    // logits role: items t and t+NT of 754.
    float po0[D], po1[D];
    float bo0 = 0.f, bo1 = 0.f;
    if (t < S * V) {
        int vi = t % V;
        bo0 = bout[vi];
        #pragma unroll
        for (int d = 0; d < D; d++) po0[d] = wout[vi * D + d];
    }
    if (t + NT < S * V) {
        int vi = (t + NT) % V;
        bo1 = bout[vi];
        #pragma unroll
        for (int d = 0; d < D; d++) po1[d] = wout[vi * D + d];
    }

    // ===== S1: fused embedding + QKV layer 0 =============================
    if (t < S * DA) {
        int s = t / DA, a = t % DA;
        int xv = x[s];
        float sk = bk0r, sq = bq0r, sv = bv0r;
        #pragma unroll
        for (int d = 0; d < D; d++) {
            float hv = emb_table[xv * D + d] + pos[s * D + d];
            sk += hv * pk0[d];
            sq += hv * pq0[d];
            sv += hv * pv0[d];
        }
        k[s][a] = sk; q[s][a] = sq * LOG2E; v[s][a] = sv;
    }
    __syncthreads();

    // ===== S2: scores 0 (t<351) ‖ vw0 (t in [352,534)) ====================
    if (t < TRI) {
        float sum = 0.f;
        #pragma unroll
        for (int a = 0; a < DA; a++) sum += q[tr][a] * k[tc][a];
        att[tr][tc] = ex2(sum);
    } else if (t >= VWB && t < VWB + S * D) {
        int j = t - VWB, c = j / D, d = j % D;
        float acc = 0.f;
        #pragma unroll
        for (int a = 0; a < DA; a++) acc += v[c][a] * pw0[a];
        vw[c][d] = acc;
    }
    __syncthreads();

    // ===== S3: h0[s][d] = bf0 + iv * sum_c att*vw =========================
    if (t < S * D) {
        int s = t / D, d = t % D;
        float sum = 0.f, dot = 0.f;
        for (int c = 0; c <= s; c++) {
            float e = att[s][c];
            sum += e;
            dot += e * vw[c][d];
        }
        h[s][d] = bf0r + rcpa(sum) * dot;
    }
    __syncthreads();

    // ===== S4: QKV layer 1 ================================================
    if (t < S * DA) {
        int s = t / DA, a = t % DA;
        float sk = bk1r, sq = bq1r, sv = bv1r;
        #pragma unroll
        for (int d = 0; d < D; d++) {
            float hv = h[s][d];
            sk += hv * pk1[d];
            sq += hv * pq1[d];
            sv += hv * pv1[d];
        }
        k[s][a] = sk; q[s][a] = sq * LOG2E; v[s][a] = sv;
    }
    __syncthreads();

    // ===== S5: scores 1 ‖ vw1 =============================================
    if (t < TRI) {
        float sum = 0.f;
        #pragma unroll
        for (int a = 0; a < DA; a++) sum += q[tr][a] * k[tc][a];
        att[tr][tc] = ex2(sum);
    } else if (t >= VWB && t < VWB + S * D) {
        int j = t - VWB, c = j / D, d = j % D;
        float acc = 0.f;
        #pragma unroll
        for (int a = 0; a < DA; a++) acc += v[c][a] * pw1[a];
        vw[c][d] = acc;
    }
    __syncthreads();

    // ===== S6: h1 + write normalized att rows (iv known locally) ==========
    if (t < S * D) {
        int s = t / D, d = t % D;
        float sum = 0.f, dot = 0.f;
        for (int c = 0; c <= s; c++) {
            float e = att[s][c];
            sum += e;
            dot += e * vw[c][d];
        }
        float iv = rcpa(sum);
        h[s][d] = bf1r + iv * dot;
        // 7 threads per row cover 26 att columns (4 each, stride 7)
        #pragma unroll
        for (int cc = d; cc < S; cc += D)
            out[S * V + s * S + cc] = (cc <= s) ? att[s][cc] * iv : 0.f;
    }
    __syncthreads();

    // ===== S7: logits (pure smem+FMA, prefetched wout) ====================
    if (t < S * V) {
        int s = t / V;
        float r = bo0;
        #pragma unroll
        for (int d = 0; d < D; d++) r += h[s][d] * po0[d];
        out[t] = r;
    }
    if (t + NT < S * V) {
        int s = (t + NT) / V;
        float r = bo1;
        #pragma unroll
        for (int d = 0; d < D; d++) r += h[s][d] * po1[d];
        out[t + NT] = r;
    }
}

extern "C" void kernel_launch(void* const* d_in, const int* in_sizes, int n_in,
                              void* d_out, int out_size)
{
    bes_transformer_kernel<<<1, NT>>>(
        (const int*)  d_in[0],   // x
        (const float*)d_in[1],   // emb_table
        (const float*)d_in[2],   // pos
        (const float*)d_in[3],  (const float*)d_in[4],   // w_k0, b_k0
        (const float*)d_in[5],  (const float*)d_in[6],   // w_q0, b_q0
        (const float*)d_in[7],  (const float*)d_in[8],   // w_v0, b_v0
        (const float*)d_in[9],  (const float*)d_in[10],  // w_f0, b_f0
        (const float*)d_in[11], (const float*)d_in[12],  // w_k1, b_k1
        (const float*)d_in[13], (const float*)d_in[14],  // w_q1, b_q1
        (const float*)d_in[15], (const float*)d_in[16],  // w_v1, b_v1
        (const float*)d_in[17], (const float*)d_in[18],  // w_f1, b_f1
        (const float*)d_in[19], (const float*)d_in[20],  // w_out, b_out
        (float*)d_out);
}

// round 16
// speedup vs baseline: 1.0500x; 1.0500x over previous
#include <cuda_runtime.h>

#define S 26
#define D 7
#define DA 11
#define V 29
#define NT 384
#define TRI (S*(S+1)/2)   // 351
#define AP 28             // att row padded to 28 floats (112B, 16B-aligned)
#define LOG2E 1.4426950408889634f

__device__ __forceinline__ float ex2(float x) {
    float y; asm("ex2.approx.f32 %0, %1;" : "=f"(y) : "f"(x)); return y;
}
__device__ __forceinline__ float rcpa(float x) {
    float y; asm("rcp.approx.f32 %0, %1;" : "=f"(y) : "f"(x)); return y;
}

__global__ __launch_bounds__(NT, 1)
void bes_transformer_kernel(
    const int*   __restrict__ x,
    const float* __restrict__ emb_table,
    const float* __restrict__ pos,
    const float* __restrict__ wk0, const float* __restrict__ bk0,
    const float* __restrict__ wq0, const float* __restrict__ bq0,
    const float* __restrict__ wv0, const float* __restrict__ bv0,
    const float* __restrict__ wf0, const float* __restrict__ bf0,
    const float* __restrict__ wk1, const float* __restrict__ bk1,
    const float* __restrict__ wq1, const float* __restrict__ bq1,
    const float* __restrict__ wv1, const float* __restrict__ bv1,
    const float* __restrict__ wf1, const float* __restrict__ bf1,
    const float* __restrict__ wout, const float* __restrict__ bout,
    float* __restrict__ out)
{
    __shared__ float h[S][D];
    __shared__ float k[S][DA];
    __shared__ float q[S][DA];                     // pre-scaled by log2(e)
    __shared__ float v[S][DA];
    __shared__ __align__(16) float att[S][AP];     // zeroed; lower tri overwritten
    __shared__ float res[S][DA];

    const int t = threadIdx.x;

    // packed lower-triangle coords (t < TRI)
    int tr = 0, tc = 0;
    if (t < TRI) {
        tr = (int)((sqrtf(8.f * (float)t + 1.f) - 1.f) * 0.5f);
        if (t < tr * (tr + 1) / 2) tr--;
        if (t >= (tr + 1) * (tr + 2) / 2) tr++;
        tc = t - tr * (tr + 1) / 2;
    }

    // ===== entry-time register prefetch per role =========================
    float pk0[D], pq0[D], pv0[D], pk1[D], pq1[D], pv1[D];
    float bk0r = 0.f, bq0r = 0.f, bv0r = 0.f, bk1r = 0.f, bq1r = 0.f, bv1r = 0.f;
    if (t < S * DA) {
        int a = t % DA;
        #pragma unroll
        for (int d = 0; d < D; d++) {
            pk0[d] = wk0[a * D + d];
            pq0[d] = wq0[a * D + d];
            pv0[d] = wv0[a * D + d];
            pk1[d] = wk1[a * D + d];
            pq1[d] = wq1[a * D + d];
            pv1[d] = wv1[a * D + d];
        }
        bk0r = bk0[a]; bq0r = bq0[a]; bv0r = bv0[a];
        bk1r = bk1[a]; bq1r = bq1[a]; bv1r = bv1[a];
    }
    float pf0[DA], pf1[DA];
    float bf0r = 0.f, bf1r = 0.f;
    if (t < S * D) {
        int d = t % D;
        #pragma unroll
        for (int a = 0; a < DA; a++) {
            pf0[a] = wf0[d * DA + a];
            pf1[a] = wf1[d * DA + a];
        }
        bf0r = bf0[d]; bf1r = bf1[d];
    }
    float po0[D], po1[D];
    float bo0 = 0.f, bo1 = 0.f;
    {
        int vi = t % V;
        bo0 = bout[vi];
        #pragma unroll
        for (int d = 0; d < D; d++) po0[d] = wout[vi * D + d];
        if (t + NT < S * V) {
            int vj = (t + NT) % V;
            bo1 = bout[vj];
            #pragma unroll
            for (int d = 0; d < D; d++) po1[d] = wout[vj * D + d];
        }
    }

    // zero att (728 floats; upper triangle + padding stay zero forever)
    {
        float* ap = &att[0][0];
        ap[t] = 0.f;
        if (t + NT < S * AP) ap[t + NT] = 0.f;
    }

    // ===== S1: fused embedding + QKV layer 0 =============================
    if (t < S * DA) {
        int s = t / DA, a = t % DA;
        int xv = x[s];
        float kA = bk0r, kB = 0.f, qA = bq0r, qB = 0.f, vA = bv0r, vB = 0.f;
        #pragma unroll
        for (int d = 0; d < 4; d++) {
            float hv = emb_table[xv * D + d] + pos[s * D + d];
            kA += hv * pk0[d]; qA += hv * pq0[d]; vA += hv * pv0[d];
        }
        #pragma unroll
        for (int d = 4; d < D; d++) {
            float hv = emb_table[xv * D + d] + pos[s * D + d];
            kB += hv * pk0[d]; qB += hv * pq0[d]; vB += hv * pv0[d];
        }
        k[s][a] = kA + kB; q[s][a] = (qA + qB) * LOG2E; v[s][a] = vA + vB;
    }
    __syncthreads();

    // ===== S2: scores 0 (packed triangle, split chains, ex2) ==============
    if (t < TRI) {
        float sA = 0.f, sB = 0.f;
        #pragma unroll
        for (int a = 0; a < 6; a++)  sA += q[tr][a] * k[tc][a];
        #pragma unroll
        for (int a = 6; a < DA; a++) sB += q[tr][a] * k[tc][a];
        att[tr][tc] = ex2(sA + sB);
    }
    __syncthreads();

    // ===== S3: AV0 + normalize (float4 att, 4-way partials) ===============
    if (t < S * DA) {
        int s = t / DA, a = t % DA;
        const float4* arow = reinterpret_cast<const float4*>(att[s]);
        float s0 = 0.f, s1 = 0.f, s2 = 0.f, s3 = 0.f;
        float d0 = 0.f, d1 = 0.f, d2 = 0.f, d3 = 0.f;
        #pragma unroll
        for (int j = 0; j < 6; j++) {
            float4 e = arow[j];
            int c = 4 * j;
            s0 += e.x; d0 += e.x * v[c + 0][a];
            s1 += e.y; d1 += e.y * v[c + 1][a];
            s2 += e.z; d2 += e.z * v[c + 2][a];
            s3 += e.w; d3 += e.w * v[c + 3][a];
        }
        {
            float4 e = arow[6];
            s0 += e.x; d0 += e.x * v[24][a];
            s1 += e.y; d1 += e.y * v[25][a];
        }
        float sum = (s0 + s1) + (s2 + s3);
        float dot = (d0 + d1) + (d2 + d3);
        res[s][a] = dot * rcpa(sum);
    }
    __syncthreads();

    // ===== S4: proj0 -> h (split chains) ==================================
    if (t < S * D) {
        int s = t / D;
        float rA = bf0r, rB = 0.f;
        #pragma unroll
        for (int a = 0; a < 6; a++)  rA += res[s][a] * pf0[a];
        #pragma unroll
        for (int a = 6; a < DA; a++) rB += res[s][a] * pf0[a];
        h[s][t % D] = rA + rB;
    }
    __syncthreads();

    // ===== S5: QKV layer 1 ================================================
    if (t < S * DA) {
        int s = t / DA, a = t % DA;
        float kA = bk1r, kB = 0.f, qA = bq1r, qB = 0.f, vA = bv1r, vB = 0.f;
        #pragma unroll
        for (int d = 0; d < 4; d++) {
            float hv = h[s][d];
            kA += hv * pk1[d]; qA += hv * pq1[d]; vA += hv * pv1[d];
        }
        #pragma unroll
        for (int d = 4; d < D; d++) {
            float hv = h[s][d];
            kB += hv * pk1[d]; qB += hv * pq1[d]; vB += hv * pv1[d];
        }
        k[s][a] = kA + kB; q[s][a] = (qA + qB) * LOG2E; v[s][a] = vA + vB;
    }
    __syncthreads();

    // ===== S6: scores 1 ===================================================
    if (t < TRI) {
        float sA = 0.f, sB = 0.f;
        #pragma unroll
        for (int a = 0; a < 6; a++)  sA += q[tr][a] * k[tc][a];
        #pragma unroll
        for (int a = 6; a < DA; a++) sB += q[tr][a] * k[tc][a];
        att[tr][tc] = ex2(sA + sB);
    }
    __syncthreads();

    // ===== S7: AV1 + normalize + direct normalized-att output =============
    if (t < S * DA) {
        int s = t / DA, a = t % DA;
        const float4* arow = reinterpret_cast<const float4*>(att[s]);
        float s0 = 0.f, s1 = 0.f, s2 = 0.f, s3 = 0.f;
        float d0 = 0.f, d1 = 0.f, d2 = 0.f, d3 = 0.f;
        #pragma unroll
        for (int j = 0; j < 6; j++) {
            float4 e = arow[j];
            int c = 4 * j;
            s0 += e.x; d0 += e.x * v[c + 0][a];
            s1 += e.y; d1 += e.y * v[c + 1][a];
            s2 += e.z; d2 += e.z * v[c + 2][a];
            s3 += e.w; d3 += e.w * v[c + 3][a];
        }
        {
            float4 e = arow[6];
            s0 += e.x; d0 += e.x * v[24][a];
            s1 += e.y; d1 += e.y * v[25][a];
        }
        float sum = (s0 + s1) + (s2 + s3);
        float dot = (d0 + d1) + (d2 + d3);
        float iv = rcpa(sum);
        res[s][a] = dot * iv;
        // every AV thread knows iv: write normalized att columns {a, a+11, a+22}
        #pragma unroll
        for (int c = a; c < S; c += DA)
            out[S * V + s * S + c] = att[s][c] * iv;   // upper tri is 0
    }
    __syncthreads();

    // ===== S8: proj1 -> h =================================================
    if (t < S * D) {
        int s = t / D;
        float rA = bf1r, rB = 0.f;
        #pragma unroll
        for (int a = 0; a < 6; a++)  rA += res[s][a] * pf1[a];
        #pragma unroll
        for (int a = 6; a < DA; a++) rB += res[s][a] * pf1[a];
        h[s][t % D] = rA + rB;
    }
    __syncthreads();

    // ===== S9: logits (pure smem+FMA, prefetched wout) ====================
    {
        int s = t / V;
        float r = bo0;
        #pragma unroll
        for (int d = 0; d < D; d++) r += h[s][d] * po0[d];
        out[t] = r;
    }
    if (t + NT < S * V) {
        int s = (t + NT) / V;
        float r = bo1;
        #pragma unroll
        for (int d = 0; d < D; d++) r += h[s][d] * po1[d];
        out[t + NT] = r;
    }
}

extern "C" void kernel_launch(void* const* d_in, const int* in_sizes, int n_in,
                              void* d_out, int out_size)
{
    bes_transformer_kernel<<<1, NT>>>(
        (const int*)  d_in[0],   // x
        (const float*)d_in[1],   // emb_table
        (const float*)d_in[2],   // pos
        (const float*)d_in[3],  (const float*)d_in[4],   // w_k0, b_k0
        (const float*)d_in[5],  (const float*)d_in[6],   // w_q0, b_q0
        (const float*)d_in[7],  (const float*)d_in[8],   // w_v0, b_v0
        (const float*)d_in[9],  (const float*)d_in[10],  // w_f0, b_f0
        (const float*)d_in[11], (const float*)d_in[12],  // w_k1, b_k1
        (const float*)d_in[13], (const float*)d_in[14],  // w_q1, b_q1
        (const float*)d_in[15], (const float*)d_in[16],  // w_v1, b_v1
        (const float*)d_in[17], (const float*)d_in[18],  // w_f1, b_f1
        (const float*)d_in[19], (const float*)d_in[20],  // w_out, b_out
        (float*)d_out);
}

// round 17
// speedup vs baseline: 1.0664x; 1.0156x over previous
#include <cuda_runtime.h>

#define S 26
#define D 7
#define DA 11
#define V 29
#define NT 384
#define TRI (S*(S+1)/2)   // 351
#define AP 28             // att row padded to 28 floats (112B, 16B-aligned)
#define LOG2E 1.4426950408889634f

__device__ __forceinline__ float ex2(float x) {
    float y; asm("ex2.approx.f32 %0, %1;" : "=f"(y) : "f"(x)); return y;
}
__device__ __forceinline__ float rcpa(float x) {
    float y; asm("rcp.approx.f32 %0, %1;" : "=f"(y) : "f"(x)); return y;
}

__global__ __launch_bounds__(NT, 1)
void bes_transformer_kernel(
    const int*   __restrict__ x,
    const float* __restrict__ emb_table,
    const float* __restrict__ pos,
    const float* __restrict__ wk0, const float* __restrict__ bk0,
    const float* __restrict__ wq0, const float* __restrict__ bq0,
    const float* __restrict__ wv0, const float* __restrict__ bv0,
    const float* __restrict__ wf0, const float* __restrict__ bf0,
    const float* __restrict__ wk1, const float* __restrict__ bk1,
    const float* __restrict__ wq1, const float* __restrict__ bq1,
    const float* __restrict__ wv1, const float* __restrict__ bv1,
    const float* __restrict__ wf1, const float* __restrict__ bf1,
    const float* __restrict__ wout, const float* __restrict__ bout,
    float* __restrict__ out)
{
    __shared__ float h[S][D];
    __shared__ float k[S][DA];
    __shared__ float q[S][DA];                     // pre-scaled by log2(e)
    __shared__ float v[S][DA];
    __shared__ __align__(16) float att[S][AP];     // zeroed; lower tri overwritten
    __shared__ float res[S][DA];
    __shared__ float embs[V * D];                  // staged embedding table
    __shared__ float poss[S * D];                  // staged positional
    __shared__ int   xs[S];                        // staged token ids

    const int t = threadIdx.x;

    // packed lower-triangle coords (t < TRI)
    int tr = 0, tc = 0;
    if (t < TRI) {
        tr = (int)((sqrtf(8.f * (float)t + 1.f) - 1.f) * 0.5f);
        if (t < tr * (tr + 1) / 2) tr--;
        if (t >= (tr + 1) * (tr + 2) / 2) tr++;
        tc = t - tr * (tr + 1) / 2;
    }

    // ===== entry: stage x/emb/pos to smem (independent, coalesced) ========
    if (t < S) xs[t] = x[t];
    if (t < V * D) embs[t] = emb_table[t];
    if (t < S * D) poss[t] = pos[t];

    // ===== entry-time register prefetch per role =========================
    float pk0[D], pq0[D], pv0[D], pk1[D], pq1[D], pv1[D];
    float bk0r = 0.f, bq0r = 0.f, bv0r = 0.f, bk1r = 0.f, bq1r = 0.f, bv1r = 0.f;
    if (t < S * DA) {
        int a = t % DA;
        #pragma unroll
        for (int d = 0; d < D; d++) {
            pk0[d] = wk0[a * D + d];
            pq0[d] = wq0[a * D + d];
            pv0[d] = wv0[a * D + d];
            pk1[d] = wk1[a * D + d];
            pq1[d] = wq1[a * D + d];
            pv1[d] = wv1[a * D + d];
        }
        bk0r = bk0[a]; bq0r = bq0[a]; bv0r = bv0[a];
        bk1r = bk1[a]; bq1r = bq1[a]; bv1r = bv1[a];
    }
    float pf0[DA], pf1[DA];
    float bf0r = 0.f, bf1r = 0.f;
    if (t < S * D) {
        int d = t % D;
        #pragma unroll
        for (int a = 0; a < DA; a++) {
            pf0[a] = wf0[d * DA + a];
            pf1[a] = wf1[d * DA + a];
        }
        bf0r = bf0[d]; bf1r = bf1[d];
    }
    float po0[D], po1[D];
    float bo0 = 0.f, bo1 = 0.f;
    {
        int vi = t % V;
        bo0 = bout[vi];
        #pragma unroll
        for (int d = 0; d < D; d++) po0[d] = wout[vi * D + d];
        if (t + NT < S * V) {
            int vj = (t + NT) % V;
            bo1 = bout[vj];
            #pragma unroll
            for (int d = 0; d < D; d++) po1[d] = wout[vj * D + d];
        }
    }

    // zero att (728 floats; upper triangle + padding stay zero forever)
    {
        float* ap = &att[0][0];
        ap[t] = 0.f;
        if (t + NT < S * AP) ap[t + NT] = 0.f;
    }
    __syncthreads();   // S0: staged emb/pos/x + zeroed att visible

    // ===== S1: fused embedding + QKV layer 0 (pure smem) ==================
    if (t < S * DA) {
        int s = t / DA, a = t % DA;
        int xv = xs[s];
        float kA = bk0r, kB = 0.f, qA = bq0r, qB = 0.f, vA = bv0r, vB = 0.f;
        #pragma unroll
        for (int d = 0; d < 4; d++) {
            float hv = embs[xv * D + d] + poss[s * D + d];
            kA += hv * pk0[d]; qA += hv * pq0[d]; vA += hv * pv0[d];
        }
        #pragma unroll
        for (int d = 4; d < D; d++) {
            float hv = embs[xv * D + d] + poss[s * D + d];
            kB += hv * pk0[d]; qB += hv * pq0[d]; vB += hv * pv0[d];
        }
        k[s][a] = kA + kB; q[s][a] = (qA + qB) * LOG2E; v[s][a] = vA + vB;
    }
    __syncthreads();

    // ===== S2: scores 0 (packed triangle, split chains, ex2) ==============
    if (t < TRI) {
        float sA = 0.f, sB = 0.f;
        #pragma unroll
        for (int a = 0; a < 6; a++)  sA += q[tr][a] * k[tc][a];
        #pragma unroll
        for (int a = 6; a < DA; a++) sB += q[tr][a] * k[tc][a];
        att[tr][tc] = ex2(sA + sB);
    }
    __syncthreads();

    // ===== S3: AV0 + normalize (float4 att, 4-way partials) ===============
    if (t < S * DA) {
        int s = t / DA, a = t % DA;
        const float4* arow = reinterpret_cast<const float4*>(att[s]);
        float s0 = 0.f, s1 = 0.f, s2 = 0.f, s3 = 0.f;
        float d0 = 0.f, d1 = 0.f, d2 = 0.f, d3 = 0.f;
        #pragma unroll
        for (int j = 0; j < 6; j++) {
            float4 e = arow[j];
            int c = 4 * j;
            s0 += e.x; d0 += e.x * v[c + 0][a];
            s1 += e.y; d1 += e.y * v[c + 1][a];
            s2 += e.z; d2 += e.z * v[c + 2][a];
            s3 += e.w; d3 += e.w * v[c + 3][a];
        }
        {
            float4 e = arow[6];
            s0 += e.x; d0 += e.x * v[24][a];
            s1 += e.y; d1 += e.y * v[25][a];
        }
        float sum = (s0 + s1) + (s2 + s3);
        float dot = (d0 + d1) + (d2 + d3);
        res[s][a] = dot * rcpa(sum);
    }
    __syncthreads();

    // ===== S4: proj0 -> h (split chains) ==================================
    if (t < S * D) {
        int s = t / D;
        float rA = bf0r, rB = 0.f;
        #pragma unroll
        for (int a = 0; a < 6; a++)  rA += res[s][a] * pf0[a];
        #pragma unroll
        for (int a = 6; a < DA; a++) rB += res[s][a] * pf0[a];
        h[s][t % D] = rA + rB;
    }
    __syncthreads();

    // ===== S5: QKV layer 1 ================================================
    if (t < S * DA) {
        int s = t / DA, a = t % DA;
        float kA = bk1r, kB = 0.f, qA = bq1r, qB = 0.f, vA = bv1r, vB = 0.f;
        #pragma unroll
        for (int d = 0; d < 4; d++) {
            float hv = h[s][d];
            kA += hv * pk1[d]; qA += hv * pq1[d]; vA += hv * pv1[d];
        }
        #pragma unroll
        for (int d = 4; d < D; d++) {
            float hv = h[s][d];
            kB += hv * pk1[d]; qB += hv * pq1[d]; vB += hv * pv1[d];
        }
        k[s][a] = kA + kB; q[s][a] = (qA + qB) * LOG2E; v[s][a] = vA + vB;
    }
    __syncthreads();

    // ===== S6: scores 1 ===================================================
    if (t < TRI) {
        float sA = 0.f, sB = 0.f;
        #pragma unroll
        for (int a = 0; a < 6; a++)  sA += q[tr][a] * k[tc][a];
        #pragma unroll
        for (int a = 6; a < DA; a++) sB += q[tr][a] * k[tc][a];
        att[tr][tc] = ex2(sA + sB);
    }
    __syncthreads();

    // ===== S7: AV1 + normalize + direct normalized-att output =============
    if (t < S * DA) {
        int s = t / DA, a = t % DA;
        const float4* arow = reinterpret_cast<const float4*>(att[s]);
        float s0 = 0.f, s1 = 0.f, s2 = 0.f, s3 = 0.f;
        float d0 = 0.f, d1 = 0.f, d2 = 0.f, d3 = 0.f;
        #pragma unroll
        for (int j = 0; j < 6; j++) {
            float4 e = arow[j];
            int c = 4 * j;
            s0 += e.x; d0 += e.x * v[c + 0][a];
            s1 += e.y; d1 += e.y * v[c + 1][a];
            s2 += e.z; d2 += e.z * v[c + 2][a];
            s3 += e.w; d3 += e.w * v[c + 3][a];
        }
        {
            float4 e = arow[6];
            s0 += e.x; d0 += e.x * v[24][a];
            s1 += e.y; d1 += e.y * v[25][a];
        }
        float sum = (s0 + s1) + (s2 + s3);
        float dot = (d0 + d1) + (d2 + d3);
        float iv = rcpa(sum);
        res[s][a] = dot * iv;
        // every AV thread knows iv: write normalized att columns {a, a+11, a+22}
        #pragma unroll
        for (int c = a; c < S; c += DA)
            out[S * V + s * S + c] = att[s][c] * iv;   // upper tri is 0
    }
    __syncthreads();

    // ===== S8: proj1 -> h =================================================
    if (t < S * D) {
        int s = t / D;
        float rA = bf1r, rB = 0.f;
        #pragma unroll
        for (int a = 0; a < 6; a++)  rA += res[s][a] * pf1[a];
        #pragma unroll
        for (int a = 6; a < DA; a++) rB += res[s][a] * pf1[a];
        h[s][t % D] = rA + rB;
    }
    __syncthreads();

    // ===== S9: logits (pure smem+FMA, prefetched wout) ====================
    {
        int s = t / V;
        float r = bo0;
        #pragma unroll
        for (int d = 0; d < D; d++) r += h[s][d] * po0[d];
        out[t] = r;
    }
    if (t + NT < S * V) {
        int s = (t + NT) / V;
        float r = bo1;
        #pragma unroll
        for (int d = 0; d < D; d++) r += h[s][d] * po1[d];
        out[t + NT] = r;
    }
}

extern "C" void kernel_launch(void* const* d_in, const int* in_sizes, int n_in,
                              void* d_out, int out_size)
{
    bes_transformer_kernel<<<1, NT>>>(
        (const int*)  d_in[0],   // x
        (const float*)d_in[1],   // emb_table
        (const float*)d_in[2],   // pos
        (const float*)d_in[3],  (const float*)d_in[4],   // w_k0, b_k0
        (const float*)d_in[5],  (const float*)d_in[6],   // w_q0, b_q0
        (const float*)d_in[7],  (const float*)d_in[8],   // w_v0, b_v0
        (const float*)d_in[9],  (const float*)d_in[10],  // w_f0, b_f0
        (const float*)d_in[11], (const float*)d_in[12],  // w_k1, b_k1
        (const float*)d_in[13], (const float*)d_in[14],  // w_q1, b_q1
        (const float*)d_in[15], (const float*)d_in[16],  // w_v1, b_v1
        (const float*)d_in[17], (const float*)d_in[18],  // w_f1, b_f1
        (const float*)d_in[19], (const float*)d_in[20],  // w_out, b_out
        (float*)d_out);
}